// round 1
// baseline (speedup 1.0000x reference)
#include <cuda_runtime.h>
#include <math.h>

// ---------------------------------------------------------------------------
// MultiHeadAttention: out = proj( softmax(QK^T/sqrt(d)) V ) with Q,K,V all
// derived from `query` (reference ignores key/value args).
//
// Pipeline:
//   1) sgemm_nt<1>:  qkv = query @ w_qkv^T, scattered into per-head [B,H,S,d]
//   2) attn_fwd:     flash-attention fp32 per (b,h), BQ=64 / BK=32
//   3) sgemm_nt<2>:  out = attn @ w_out^T + b_out
// ---------------------------------------------------------------------------

#define DM   1024
#define NH   16
#define HD   64
#define BB   4
#define SS   2048
#define NTOK (BB * SS)   // 8192

// Scratch (device globals: no runtime allocation allowed)
__device__ float g_qkv[(size_t)3 * NTOK * DM];   // [3][B][H][S][d]
__device__ float g_attn[(size_t)NTOK * DM];      // [B*S][H*d]

// ---------------------------------------------------------------------------
// NT SGEMM: C[i][j] = sum_k A[i][k] * B[j][k]
// 128x128 tile, BK=8, 256 threads, 8x8 per thread, double-buffered smem.
// MODE 1: A = param (query), epilogue scatters into g_qkv head layout.
// MODE 2: A = g_attn (internal), epilogue adds bias, writes C.
// ---------------------------------------------------------------------------
template <int MODE>
__global__ __launch_bounds__(256, 2)
void sgemm_nt(const float* __restrict__ A, const float* __restrict__ B,
              float* __restrict__ C, const float* __restrict__ bias,
              int M, int N, int K)
{
    __shared__ float As[2][8][128];
    __shared__ float Bs[2][8][128];

    const float* Abase = (MODE == 2) ? (const float*)g_attn : A;

    const int tid = threadIdx.x;
    const int bm  = blockIdx.y;
    const int bn  = blockIdx.x;

    const int lrow = tid >> 1;          // 0..127
    const int lcol = (tid & 1) << 2;    // 0 or 4

    const float* Ag = Abase + (size_t)(bm * 128 + lrow) * K + lcol;
    const float* Bg = B     + (size_t)(bn * 128 + lrow) * K + lcol;

    const int warp = tid >> 5;
    const int lane = tid & 31;
    const int row0 = (warp & 3) * 32 + (lane >> 3) * 8;   // 0..120
    const int col0 = (warp >> 2) * 64 + (lane & 7) * 8;   // 0..120

    float acc[8][8];
#pragma unroll
    for (int i = 0; i < 8; ++i)
#pragma unroll
        for (int j = 0; j < 8; ++j) acc[i][j] = 0.0f;

    // preload tile 0
    float4 la = *(const float4*)Ag;
    float4 lb = *(const float4*)Bg;
    As[0][lcol + 0][lrow] = la.x; As[0][lcol + 1][lrow] = la.y;
    As[0][lcol + 2][lrow] = la.z; As[0][lcol + 3][lrow] = la.w;
    Bs[0][lcol + 0][lrow] = lb.x; Bs[0][lcol + 1][lrow] = lb.y;
    Bs[0][lcol + 2][lrow] = lb.z; Bs[0][lcol + 3][lrow] = lb.w;
    __syncthreads();

    const int ktiles = K >> 3;
    for (int kt = 0; kt < ktiles; ++kt) {
        const int buf = kt & 1;
        if (kt + 1 < ktiles) {
            la = *(const float4*)(Ag + (size_t)(kt + 1) * 8);
            lb = *(const float4*)(Bg + (size_t)(kt + 1) * 8);
        }
#pragma unroll
        for (int kk = 0; kk < 8; ++kk) {
            float4 a0 = *(const float4*)&As[buf][kk][row0];
            float4 a1 = *(const float4*)&As[buf][kk][row0 + 4];
            float4 b0 = *(const float4*)&Bs[buf][kk][col0];
            float4 b1 = *(const float4*)&Bs[buf][kk][col0 + 4];
            float ar[8] = {a0.x, a0.y, a0.z, a0.w, a1.x, a1.y, a1.z, a1.w};
            float br[8] = {b0.x, b0.y, b0.z, b0.w, b1.x, b1.y, b1.z, b1.w};
#pragma unroll
            for (int i = 0; i < 8; ++i)
#pragma unroll
                for (int j = 0; j < 8; ++j)
                    acc[i][j] = fmaf(ar[i], br[j], acc[i][j]);
        }
        if (kt + 1 < ktiles) {
            const int nb = (kt + 1) & 1;
            As[nb][lcol + 0][lrow] = la.x; As[nb][lcol + 1][lrow] = la.y;
            As[nb][lcol + 2][lrow] = la.z; As[nb][lcol + 3][lrow] = la.w;
            Bs[nb][lcol + 0][lrow] = lb.x; Bs[nb][lcol + 1][lrow] = lb.y;
            Bs[nb][lcol + 2][lrow] = lb.z; Bs[nb][lcol + 3][lrow] = lb.w;
        }
        __syncthreads();
    }

    if (MODE == 1) {
        // scatter into g_qkv: [part][b][h][s][d]
        const int gj0  = bn * 128 + col0;       // 8 cols stay inside one head
        const int part = gj0 >> 10;
        const int h    = (gj0 >> 6) & (NH - 1);
        const int d0   = gj0 & (HD - 1);
        float* base = g_qkv + (size_t)part * NTOK * DM;
#pragma unroll
        for (int i = 0; i < 8; ++i) {
            const int gi = bm * 128 + row0 + i;
            const int b  = gi >> 11;
            const int s  = gi & (SS - 1);
            float* dst = base + ((size_t)((b * NH + h) * SS + s)) * HD + d0;
            *(float4*)(dst)     = make_float4(acc[i][0], acc[i][1], acc[i][2], acc[i][3]);
            *(float4*)(dst + 4) = make_float4(acc[i][4], acc[i][5], acc[i][6], acc[i][7]);
        }
    } else {
        const int gj0 = bn * 128 + col0;
        float4 bv0 = *(const float4*)&bias[gj0];
        float4 bv1 = *(const float4*)&bias[gj0 + 4];
#pragma unroll
        for (int i = 0; i < 8; ++i) {
            const int gi = bm * 128 + row0 + i;
            float* dst = C + (size_t)gi * N + gj0;
            *(float4*)(dst)     = make_float4(acc[i][0] + bv0.x, acc[i][1] + bv0.y,
                                              acc[i][2] + bv0.z, acc[i][3] + bv0.w);
            *(float4*)(dst + 4) = make_float4(acc[i][4] + bv1.x, acc[i][5] + bv1.y,
                                              acc[i][6] + bv1.z, acc[i][7] + bv1.w);
        }
    }
}

// ---------------------------------------------------------------------------
// Flash attention fp32. One block per (b, h, 64-query tile). 256 threads
// as 16x16; each thread owns 4 query rows x {2 score cols | 4 out dims}.
// ---------------------------------------------------------------------------
__global__ __launch_bounds__(256)
void attn_fwd()
{
    const int qt = blockIdx.x;
    const int h  = blockIdx.y;
    const int b  = blockIdx.z;

    const float* qbase = g_qkv + ((size_t)(b * NH + h) * SS) * HD;
    const float* kbase = qbase + (size_t)NTOK * DM;
    const float* vbase = kbase + (size_t)NTOK * DM;

    __shared__ float Qs[64][64];   // [d][r], pre-scaled by 1/sqrt(d)
    __shared__ float Ks[64][32];   // [d][c]
    __shared__ float Vs[32][64];   // [c][d]
    __shared__ float Ps[32][65];   // [c][r], padded

    const int tid = threadIdx.x;
    const int tx  = tid & 15;
    const int ty  = tid >> 4;
    const int ty4 = ty << 2;

    // load + transpose + scale Q tile
    const float scale = 0.125f;    // 1/sqrt(64)
    for (int i = tid; i < 64 * 16; i += 256) {
        const int r  = i >> 4;
        const int d4 = (i & 15) << 2;
        float4 qv = *(const float4*)(qbase + (size_t)(qt * 64 + r) * HD + d4);
        Qs[d4 + 0][r] = qv.x * scale;
        Qs[d4 + 1][r] = qv.y * scale;
        Qs[d4 + 2][r] = qv.z * scale;
        Qs[d4 + 3][r] = qv.w * scale;
    }

    float m[4], l[4], acc[4][4];
#pragma unroll
    for (int i = 0; i < 4; ++i) {
        m[i] = -INFINITY;
        l[i] = 0.0f;
#pragma unroll
        for (int j = 0; j < 4; ++j) acc[i][j] = 0.0f;
    }

    for (int kt = 0; kt < SS / 32; ++kt) {
        __syncthreads();   // prior tile consumers done (also covers Q load, tile 0)
        for (int i = tid; i < 32 * 16; i += 256) {
            const int c  = i >> 4;
            const int d4 = (i & 15) << 2;
            const size_t off = (size_t)(kt * 32 + c) * HD + d4;
            float4 kv = *(const float4*)(kbase + off);
            Ks[d4 + 0][c] = kv.x; Ks[d4 + 1][c] = kv.y;
            Ks[d4 + 2][c] = kv.z; Ks[d4 + 3][c] = kv.w;
            *(float4*)&Vs[c][d4] = *(const float4*)(vbase + off);
        }
        __syncthreads();

        // S = Q K^T (4 rows x 2 cols per thread)
        float s[4][2];
#pragma unroll
        for (int i = 0; i < 4; ++i) { s[i][0] = 0.0f; s[i][1] = 0.0f; }
#pragma unroll 16
        for (int d = 0; d < 64; ++d) {
            float4 aq = *(const float4*)&Qs[d][ty4];
            float2 bk = *(const float2*)&Ks[d][tx * 2];
            s[0][0] = fmaf(aq.x, bk.x, s[0][0]); s[0][1] = fmaf(aq.x, bk.y, s[0][1]);
            s[1][0] = fmaf(aq.y, bk.x, s[1][0]); s[1][1] = fmaf(aq.y, bk.y, s[1][1]);
            s[2][0] = fmaf(aq.z, bk.x, s[2][0]); s[2][1] = fmaf(aq.z, bk.y, s[2][1]);
            s[3][0] = fmaf(aq.w, bk.x, s[3][0]); s[3][1] = fmaf(aq.w, bk.y, s[3][1]);
        }

        // online softmax, per owned row (replicated across the 16 tx lanes)
#pragma unroll
        for (int i = 0; i < 4; ++i) {
            float tm = fmaxf(s[i][0], s[i][1]);
            tm = fmaxf(tm, __shfl_xor_sync(0xffffffffu, tm, 8));
            tm = fmaxf(tm, __shfl_xor_sync(0xffffffffu, tm, 4));
            tm = fmaxf(tm, __shfl_xor_sync(0xffffffffu, tm, 2));
            tm = fmaxf(tm, __shfl_xor_sync(0xffffffffu, tm, 1));
            const float mn    = fmaxf(m[i], tm);
            const float alpha = __expf(m[i] - mn);
            m[i] = mn;
            s[i][0] = __expf(s[i][0] - mn);
            s[i][1] = __expf(s[i][1] - mn);
            float rs = s[i][0] + s[i][1];
            rs += __shfl_xor_sync(0xffffffffu, rs, 8);
            rs += __shfl_xor_sync(0xffffffffu, rs, 4);
            rs += __shfl_xor_sync(0xffffffffu, rs, 2);
            rs += __shfl_xor_sync(0xffffffffu, rs, 1);
            l[i] = l[i] * alpha + rs;
#pragma unroll
            for (int j = 0; j < 4; ++j) acc[i][j] *= alpha;
            Ps[tx * 2 + 0][ty4 + i] = s[i][0];
            Ps[tx * 2 + 1][ty4 + i] = s[i][1];
        }
        __syncthreads();

        // O += P @ V  (4 rows x 4 dims per thread)
#pragma unroll 8
        for (int c = 0; c < 32; ++c) {
            float4 vv = *(const float4*)&Vs[c][tx * 4];
            float p0 = Ps[c][ty4 + 0];
            float p1 = Ps[c][ty4 + 1];
            float p2 = Ps[c][ty4 + 2];
            float p3 = Ps[c][ty4 + 3];
            acc[0][0] = fmaf(p0, vv.x, acc[0][0]); acc[0][1] = fmaf(p0, vv.y, acc[0][1]);
            acc[0][2] = fmaf(p0, vv.z, acc[0][2]); acc[0][3] = fmaf(p0, vv.w, acc[0][3]);
            acc[1][0] = fmaf(p1, vv.x, acc[1][0]); acc[1][1] = fmaf(p1, vv.y, acc[1][1]);
            acc[1][2] = fmaf(p1, vv.z, acc[1][2]); acc[1][3] = fmaf(p1, vv.w, acc[1][3]);
            acc[2][0] = fmaf(p2, vv.x, acc[2][0]); acc[2][1] = fmaf(p2, vv.y, acc[2][1]);
            acc[2][2] = fmaf(p2, vv.z, acc[2][2]); acc[2][3] = fmaf(p2, vv.w, acc[2][3]);
            acc[3][0] = fmaf(p3, vv.x, acc[3][0]); acc[3][1] = fmaf(p3, vv.y, acc[3][1]);
            acc[3][2] = fmaf(p3, vv.z, acc[3][2]); acc[3][3] = fmaf(p3, vv.w, acc[3][3]);
        }
    }

    // normalize + write to g_attn in [b*S+s][h*64+d] layout for the out-proj
#pragma unroll
    for (int i = 0; i < 4; ++i) {
        const float inv = 1.0f / l[i];
        const int s_glob = qt * 64 + ty4 + i;
        float* dst = g_attn + ((size_t)(b * SS + s_glob)) * DM + h * HD + tx * 4;
        *(float4*)dst = make_float4(acc[i][0] * inv, acc[i][1] * inv,
                                    acc[i][2] * inv, acc[i][3] * inv);
    }
}

// ---------------------------------------------------------------------------
extern "C" void kernel_launch(void* const* d_in, const int* in_sizes, int n_in,
                              void* d_out, int out_size)
{
    const float* query = (const float*)d_in[0];
    const float* w_qkv = (const float*)d_in[3];
    const float* w_out = (const float*)d_in[4];
    const float* b_out = (const float*)d_in[5];
    float* out = (float*)d_out;

    // 1) QKV projection: [8192,1024] x [3072,1024]^T
    {
        dim3 grid(3 * DM / 128, NTOK / 128);
        sgemm_nt<1><<<grid, 256>>>(query, w_qkv, nullptr, nullptr,
                                   NTOK, 3 * DM, DM);
    }
    // 2) attention
    {
        dim3 grid(SS / 64, NH, BB);
        attn_fwd<<<grid, 256>>>();
    }
    // 3) output projection + bias: [8192,1024] x [1024,1024]^T
    {
        dim3 grid(DM / 128, NTOK / 128);
        sgemm_nt<2><<<grid, 256>>>(nullptr, w_out, out, b_out,
                                   NTOK, DM, DM);
    }
}

// round 3
// speedup vs baseline: 3.4235x; 3.4235x over previous
#include <cuda_runtime.h>
#include <cuda_bf16.h>
#include <math.h>
#include <stdint.h>

// ---------------------------------------------------------------------------
// MHA via mma.sync (HMMA) split-bf16: x = hi + lo, product via 3 MMAs
// (hi*hi + hi*lo + lo*hi), fp32 accumulators. Error per term ~2^-16.
//
//   0) convert query / w_qkv / w_out fp32 -> split bf16
//   1) gemm_ms<1>: qkv = query @ w_qkv^T; epilogue writes split-bf16 Q,K,V in
//      per-head layout [b,h,s,d]; Q pre-scaled by 0.125*log2(e)
//   2) attn_ms:    FA2 on mma.sync; softmax in registers (exp2f); epilogue
//      writes split-bf16 attn output [tok, h*64+d]
//   3) gemm_ms<2>: out = attn @ w_out^T + b_out (fp32 out)
// ---------------------------------------------------------------------------

#define DM   1024
#define NH   16
#define HD   64
#define BB   4
#define SS   2048
#define NTOK (BB * SS)   // 8192

#define QSCALE 0.18033688011112042f   // 0.125 * log2(e)

// Scratch (device globals; no runtime allocation allowed)
__device__ __nv_bfloat16 g_a_hi[(size_t)NTOK * DM];    // query split
__device__ __nv_bfloat16 g_a_lo[(size_t)NTOK * DM];
__device__ __nv_bfloat16 g_w1_hi[(size_t)3 * DM * DM];
__device__ __nv_bfloat16 g_w1_lo[(size_t)3 * DM * DM];
__device__ __nv_bfloat16 g_w2_hi[(size_t)DM * DM];
__device__ __nv_bfloat16 g_w2_lo[(size_t)DM * DM];
__device__ __nv_bfloat16 g_q_hi[(size_t)NTOK * DM];    // [b,h,s,d]
__device__ __nv_bfloat16 g_q_lo[(size_t)NTOK * DM];
__device__ __nv_bfloat16 g_k_hi[(size_t)NTOK * DM];
__device__ __nv_bfloat16 g_k_lo[(size_t)NTOK * DM];
__device__ __nv_bfloat16 g_v_hi[(size_t)NTOK * DM];
__device__ __nv_bfloat16 g_v_lo[(size_t)NTOK * DM];
__device__ __nv_bfloat16 g_ao_hi[(size_t)NTOK * DM];   // attn out [tok][h*64+d]
__device__ __nv_bfloat16 g_ao_lo[(size_t)NTOK * DM];

// ------------------------------- helpers -----------------------------------
__device__ __forceinline__ uint32_t smem_u32(const void* p) {
    uint32_t a;
    asm("{ .reg .u64 t; cvta.to.shared.u64 t, %1; cvt.u32.u64 %0, t; }" : "=r"(a) : "l"(p));
    return a;
}
__device__ __forceinline__ void ldsm4(uint32_t* r, uint32_t a) {
    asm volatile("ldmatrix.sync.aligned.m8n8.x4.shared.b16 {%0,%1,%2,%3}, [%4];"
                 : "=r"(r[0]), "=r"(r[1]), "=r"(r[2]), "=r"(r[3]) : "r"(a));
}
__device__ __forceinline__ void ldsm4t(uint32_t* r, uint32_t a) {
    asm volatile("ldmatrix.sync.aligned.m8n8.x4.trans.shared.b16 {%0,%1,%2,%3}, [%4];"
                 : "=r"(r[0]), "=r"(r[1]), "=r"(r[2]), "=r"(r[3]) : "r"(a));
}
// D (f32 x4) += A (bf16 16x16) * B (bf16 16x8)
__device__ __forceinline__ void mma16816(float* c, const uint32_t* a, const uint32_t* b) {
    asm volatile("mma.sync.aligned.m16n8k16.row.col.f32.bf16.bf16.f32 "
                 "{%0,%1,%2,%3}, {%4,%5,%6,%7}, {%8,%9}, {%0,%1,%2,%3};"
                 : "+f"(c[0]), "+f"(c[1]), "+f"(c[2]), "+f"(c[3])
                 : "r"(a[0]), "r"(a[1]), "r"(a[2]), "r"(a[3]), "r"(b[0]), "r"(b[1]));
}
// pack two bf16 (lo -> low half)
__device__ __forceinline__ uint32_t packb(__nv_bfloat16 lo, __nv_bfloat16 hi) {
    __nv_bfloat162 t(lo, hi);
    return *(uint32_t*)&t;
}
__device__ __forceinline__ void split1(float x, __nv_bfloat16& h, __nv_bfloat16& l) {
    h = __float2bfloat16(x);
    l = __float2bfloat16(x - __bfloat162float(h));
}
// split a pair (x0 -> low lane) into packed hi-word and lo-word
__device__ __forceinline__ void split2(float x0, float x1, uint32_t& hw, uint32_t& lw) {
    __nv_bfloat16 h0, h1, l0, l1;
    split1(x0, h0, l0); split1(x1, h1, l1);
    hw = packb(h0, h1); lw = packb(l0, l1);
}

// fp32 -> split-bf16 conversion. T: 0=query, 1=w_qkv, 2=w_out
template <int T>
__global__ void convert_split(const float* __restrict__ in, int n4)
{
    __nv_bfloat16* hi = (T == 0) ? g_a_hi : (T == 1) ? g_w1_hi : g_w2_hi;
    __nv_bfloat16* lo = (T == 0) ? g_a_lo : (T == 1) ? g_w1_lo : g_w2_lo;
    int i = blockIdx.x * blockDim.x + threadIdx.x;
    if (i >= n4) return;
    float4 v = ((const float4*)in)[i];
    uint32_t h01, l01, h23, l23;
    split2(v.x, v.y, h01, l01);
    split2(v.z, v.w, h23, l23);
    uint32_t* H = (uint32_t*)hi + 2 * i;
    uint32_t* L = (uint32_t*)lo + 2 * i;
    H[0] = h01; H[1] = h23;
    L[0] = l01; L[1] = l23;
}

// ---------------------------------------------------------------------------
// mma.sync split-bf16 NT GEMM: C[i][j] = sum_k A[i][k]*B[j][k], K = 1024.
// CTA 128x128, 8 warps as 2(m) x 4(n), warp tile 64x32. smem K-chunk 64.
// MODE 1: A=query split, B=w_qkv split; epilogue -> split Q/K/V per-head.
// MODE 2: A=attn-out split, B=w_out split; epilogue -> fp32 C + bias.
// ---------------------------------------------------------------------------
#define GEMM_SMEM (4 * 128 * 72 * 2)   // 73728 B

template <int MODE>
__global__ __launch_bounds__(256, 2)
void gemm_ms(float* __restrict__ C, const float* __restrict__ bias)
{
    const __nv_bfloat16* Ah = (MODE == 1) ? g_a_hi : g_ao_hi;
    const __nv_bfloat16* Al = (MODE == 1) ? g_a_lo : g_ao_lo;
    const __nv_bfloat16* Bh = (MODE == 1) ? g_w1_hi : g_w2_hi;
    const __nv_bfloat16* Bl = (MODE == 1) ? g_w1_lo : g_w2_lo;

    extern __shared__ __align__(16) char smem[];
    const uint32_t OFF_AH = 0, OFF_AL = 18432, OFF_BH = 36864, OFF_BL = 55296;
    const uint32_t sb = smem_u32(smem);

    const int tid  = threadIdx.x;
    const int warp = tid >> 5;
    const int lane = tid & 31;
    const int wm   = warp >> 2;          // 0..1
    const int wn   = warp & 3;           // 0..3
    const int bm   = blockIdx.y;
    const int bn   = blockIdx.x;

    // lane offsets (bytes) within a fragment tile, stride 72 bf16 per row
    const uint32_t aoff = (uint32_t)(((lane & 15) * 72 + (lane >> 4) * 8) * 2);
    const uint32_t boff = (uint32_t)((((lane >> 4) * 8 + (lane & 7)) * 72 + ((lane >> 3) & 1) * 8) * 2);

    float acc[4][4][4];
#pragma unroll
    for (int i = 0; i < 4; ++i)
#pragma unroll
        for (int j = 0; j < 4; ++j)
#pragma unroll
            for (int t = 0; t < 4; ++t) acc[i][j][t] = 0.0f;

    const int ldr = tid >> 3;            // 0..31
    const int ldc = (tid & 7) * 8;       // 0..56

    for (int kt = 0; kt < 16; ++kt) {
        __syncthreads();
#pragma unroll
        for (int rr = 0; rr < 4; ++rr) {
            const int row = ldr + rr * 32;
            const size_t ga = (size_t)(bm * 128 + row) * DM + kt * 64 + ldc;
            const size_t gb = (size_t)(bn * 128 + row) * DM + kt * 64 + ldc;
            const uint32_t so = (uint32_t)((row * 72 + ldc) * 2);
            *(uint4*)(smem + OFF_AH + so) = *(const uint4*)(Ah + ga);
            *(uint4*)(smem + OFF_AL + so) = *(const uint4*)(Al + ga);
            *(uint4*)(smem + OFF_BH + so) = *(const uint4*)(Bh + gb);
            *(uint4*)(smem + OFF_BL + so) = *(const uint4*)(Bl + gb);
        }
        __syncthreads();

#pragma unroll
        for (int kd = 0; kd < 4; ++kd) {
            uint32_t ah[4][4], al[4][4];
#pragma unroll
            for (int mf = 0; mf < 4; ++mf) {
                const uint32_t base = (uint32_t)(((wm * 64 + mf * 16) * 72 + kd * 16) * 2) + aoff;
                ldsm4(ah[mf], sb + OFF_AH + base);
                ldsm4(al[mf], sb + OFF_AL + base);
            }
#pragma unroll
            for (int nb = 0; nb < 2; ++nb) {
                uint32_t bh[4], bl[4];
                const uint32_t base = (uint32_t)(((wn * 32 + nb * 16) * 72 + kd * 16) * 2) + boff;
                ldsm4(bh, sb + OFF_BH + base);
                ldsm4(bl, sb + OFF_BL + base);
#pragma unroll
                for (int mf = 0; mf < 4; ++mf) {
                    float* c0 = acc[mf][nb * 2];
                    float* c1 = acc[mf][nb * 2 + 1];
                    mma16816(c0, ah[mf], bh);
                    mma16816(c0, ah[mf], bl);
                    mma16816(c0, al[mf], bh);
                    mma16816(c1, ah[mf], bh + 2);
                    mma16816(c1, ah[mf], bl + 2);
                    mma16816(c1, al[mf], bh + 2);
                }
            }
        }
    }

    // ---- epilogue ----
    const int rbase = bm * 128 + wm * 64 + (lane >> 2);
    const int cbase = bn * 128 + wn * 32 + (lane & 3) * 2;
#pragma unroll
    for (int mf = 0; mf < 4; ++mf) {
#pragma unroll
        for (int nf = 0; nf < 4; ++nf) {
            const float* c = acc[mf][nf];
            const int gc = cbase + nf * 8;
#pragma unroll
            for (int half = 0; half < 2; ++half) {
                const int gr = rbase + mf * 16 + half * 8;
                float v0 = c[half * 2 + 0];
                float v1 = c[half * 2 + 1];
                if (MODE == 1) {
                    const int part = gc >> 10;
                    const int h    = (gc >> 6) & (NH - 1);
                    const int d    = gc & (HD - 1);
                    const int b    = gr >> 11;
                    const int s    = gr & (SS - 1);
                    if (part == 0) { v0 *= QSCALE; v1 *= QSCALE; }
                    __nv_bfloat16* dh = (part == 0) ? g_q_hi : (part == 1) ? g_k_hi : g_v_hi;
                    __nv_bfloat16* dl = (part == 0) ? g_q_lo : (part == 1) ? g_k_lo : g_v_lo;
                    const size_t off = ((size_t)((b * NH + h) * SS + s)) * HD + d;
                    uint32_t hw, lw;
                    split2(v0, v1, hw, lw);
                    *(uint32_t*)(dh + off) = hw;
                    *(uint32_t*)(dl + off) = lw;
                } else {
                    float2 bv = *(const float2*)(bias + gc);
                    *(float2*)(C + (size_t)gr * DM + gc) = make_float2(v0 + bv.x, v1 + bv.y);
                }
            }
        }
    }
}

// ---------------------------------------------------------------------------
// Flash attention on mma.sync. One CTA per (b, h, 128-row q tile); 8 warps,
// each owns 16 q rows. K-tile = 128. All operands split-bf16; S/P in regs.
// ---------------------------------------------------------------------------
#define ATTN_SMEM (6 * 128 * 72 * 2)   // 110592 B

__global__ __launch_bounds__(256, 1)
void attn_ms()
{
    const int qt = blockIdx.x;
    const int h  = blockIdx.y;
    const int b  = blockIdx.z;

    extern __shared__ __align__(16) char smem[];
    const uint32_t OFF_QH = 0,      OFF_QL = 18432;
    const uint32_t OFF_KH = 36864,  OFF_KL = 55296;
    const uint32_t OFF_VH = 73728,  OFF_VL = 92160;
    const uint32_t sb = smem_u32(smem);

    const int tid  = threadIdx.x;
    const int warp = tid >> 5;
    const int lane = tid & 31;

    const size_t hb = (size_t)(b * NH + h) * SS * HD;

    // lane fragment offsets (bytes), stride 72 bf16
    const uint32_t aoff = (uint32_t)(((lane & 15) * 72 + (lane >> 4) * 8) * 2);
    const uint32_t boff = (uint32_t)((((lane >> 4) * 8 + (lane & 7)) * 72 + ((lane >> 3) & 1) * 8) * 2);
    const uint32_t voff = (uint32_t)((((lane & 7) + ((lane >> 3) & 1) * 8) * 72 + (lane >> 4) * 8) * 2);

    // ---- load Q tile (128 x 64, hi/lo) ----
    {
        const int r = tid >> 3, c = (tid & 7) * 8;
#pragma unroll
        for (int rr = 0; rr < 4; ++rr) {
            const int row = r + rr * 32;
            const size_t g = hb + (size_t)(qt * 128 + row) * HD + c;
            const uint32_t so = (uint32_t)((row * 72 + c) * 2);
            *(uint4*)(smem + OFF_QH + so) = *(const uint4*)(g_q_hi + g);
            *(uint4*)(smem + OFF_QL + so) = *(const uint4*)(g_q_lo + g);
        }
    }
    __syncthreads();

    // Q fragments for this warp's 16 rows
    uint32_t qh[4][4], ql[4][4];
#pragma unroll
    for (int kd = 0; kd < 4; ++kd) {
        const uint32_t base = (uint32_t)(((warp * 16) * 72 + kd * 16) * 2) + aoff;
        ldsm4(qh[kd], sb + OFF_QH + base);
        ldsm4(ql[kd], sb + OFF_QL + base);
    }

    float o[8][4];
#pragma unroll
    for (int j = 0; j < 8; ++j)
#pragma unroll
        for (int t = 0; t < 4; ++t) o[j][t] = 0.0f;
    float m0 = -1e30f, m1 = -1e30f, l0 = 0.0f, l1 = 0.0f;

    for (int kt = 0; kt < SS / 128; ++kt) {
        __syncthreads();
        {
            const int r = tid >> 3, c = (tid & 7) * 8;
#pragma unroll
            for (int rr = 0; rr < 4; ++rr) {
                const int row = r + rr * 32;
                const size_t g = hb + (size_t)(kt * 128 + row) * HD + c;
                const uint32_t so = (uint32_t)((row * 72 + c) * 2);
                *(uint4*)(smem + OFF_KH + so) = *(const uint4*)(g_k_hi + g);
                *(uint4*)(smem + OFF_KL + so) = *(const uint4*)(g_k_lo + g);
                *(uint4*)(smem + OFF_VH + so) = *(const uint4*)(g_v_hi + g);
                *(uint4*)(smem + OFF_VL + so) = *(const uint4*)(g_v_lo + g);
            }
        }
        __syncthreads();

        // ---- S = Q K^T (16 x 128 per warp, log2-scaled) ----
        float s[16][4];
#pragma unroll
        for (int j = 0; j < 16; ++j)
#pragma unroll
            for (int t = 0; t < 4; ++t) s[j][t] = 0.0f;

#pragma unroll
        for (int kd = 0; kd < 4; ++kd) {
#pragma unroll
            for (int nb = 0; nb < 8; ++nb) {
                uint32_t bh[4], bl[4];
                const uint32_t base = (uint32_t)(((nb * 16) * 72 + kd * 16) * 2) + boff;
                ldsm4(bh, sb + OFF_KH + base);
                ldsm4(bl, sb + OFF_KL + base);
                float* c0 = s[nb * 2];
                float* c1 = s[nb * 2 + 1];
                mma16816(c0, qh[kd], bh);
                mma16816(c0, qh[kd], bl);
                mma16816(c0, ql[kd], bh);
                mma16816(c1, qh[kd], bh + 2);
                mma16816(c1, qh[kd], bl + 2);
                mma16816(c1, ql[kd], bh + 2);
            }
        }

        // ---- online softmax (rows r = warp*16 + lane/4 and +8) ----
        float mt0 = -1e30f, mt1 = -1e30f;
#pragma unroll
        for (int j = 0; j < 16; ++j) {
            mt0 = fmaxf(mt0, fmaxf(s[j][0], s[j][1]));
            mt1 = fmaxf(mt1, fmaxf(s[j][2], s[j][3]));
        }
        mt0 = fmaxf(mt0, __shfl_xor_sync(0xffffffffu, mt0, 1));
        mt0 = fmaxf(mt0, __shfl_xor_sync(0xffffffffu, mt0, 2));
        mt1 = fmaxf(mt1, __shfl_xor_sync(0xffffffffu, mt1, 1));
        mt1 = fmaxf(mt1, __shfl_xor_sync(0xffffffffu, mt1, 2));

        const float mn0 = fmaxf(m0, mt0);
        const float mn1 = fmaxf(m1, mt1);
        const float al0 = exp2f(m0 - mn0);
        const float al1 = exp2f(m1 - mn1);
        m0 = mn0; m1 = mn1;

        float rs0 = 0.0f, rs1 = 0.0f;
#pragma unroll
        for (int j = 0; j < 16; ++j) {
            s[j][0] = exp2f(s[j][0] - mn0);
            s[j][1] = exp2f(s[j][1] - mn0);
            s[j][2] = exp2f(s[j][2] - mn1);
            s[j][3] = exp2f(s[j][3] - mn1);
            rs0 += s[j][0] + s[j][1];
            rs1 += s[j][2] + s[j][3];
        }
        rs0 += __shfl_xor_sync(0xffffffffu, rs0, 1);
        rs0 += __shfl_xor_sync(0xffffffffu, rs0, 2);
        rs1 += __shfl_xor_sync(0xffffffffu, rs1, 1);
        rs1 += __shfl_xor_sync(0xffffffffu, rs1, 2);
        l0 = l0 * al0 + rs0;
        l1 = l1 * al1 + rs1;

#pragma unroll
        for (int j = 0; j < 8; ++j) {
            o[j][0] *= al0; o[j][1] *= al0;
            o[j][2] *= al1; o[j][3] *= al1;
        }

        // ---- split P into A-fragments, in place over s ----
        // frag kc: hi words -> s[2kc][0..3], lo words -> s[2kc+1][0..3]
#pragma unroll
        for (int kc = 0; kc < 8; ++kc) {
            float f0 = s[2*kc][0], f1 = s[2*kc][1], f2 = s[2*kc][2], f3 = s[2*kc][3];
            float g0 = s[2*kc+1][0], g1 = s[2*kc+1][1], g2 = s[2*kc+1][2], g3 = s[2*kc+1][3];
            uint32_t h01, l01, h23, l23, hg01, lg01, hg23, lg23;
            split2(f0, f1, h01, l01);
            split2(f2, f3, h23, l23);
            split2(g0, g1, hg01, lg01);
            split2(g2, g3, hg23, lg23);
            s[2*kc][0]   = __uint_as_float(h01);
            s[2*kc][1]   = __uint_as_float(h23);
            s[2*kc][2]   = __uint_as_float(hg01);
            s[2*kc][3]   = __uint_as_float(hg23);
            s[2*kc+1][0] = __uint_as_float(l01);
            s[2*kc+1][1] = __uint_as_float(l23);
            s[2*kc+1][2] = __uint_as_float(lg01);
            s[2*kc+1][3] = __uint_as_float(lg23);
        }

        // ---- O += P V ----
#pragma unroll
        for (int dn = 0; dn < 4; ++dn) {
#pragma unroll
            for (int kc = 0; kc < 8; ++kc) {
                uint32_t vh[4], vl[4];
                const uint32_t base = (uint32_t)(((kc * 16) * 72 + dn * 16) * 2) + voff;
                ldsm4t(vh, sb + OFF_VH + base);
                ldsm4t(vl, sb + OFF_VL + base);
                const uint32_t* ph = (const uint32_t*)s[2*kc];
                const uint32_t* pl = (const uint32_t*)s[2*kc+1];
                float* c0 = o[dn * 2];
                float* c1 = o[dn * 2 + 1];
                mma16816(c0, ph, vh);
                mma16816(c0, ph, vl);
                mma16816(c0, pl, vh);
                mma16816(c1, ph, vh + 2);
                mma16816(c1, ph, vl + 2);
                mma16816(c1, pl, vh + 2);
            }
        }
    }

    // ---- epilogue: normalize, split-bf16 store to g_ao ----
    const float inv0 = 1.0f / l0;
    const float inv1 = 1.0f / l1;
    const int r0 = qt * 128 + warp * 16 + (lane >> 2);
    const int cb = h * HD + (lane & 3) * 2;
#pragma unroll
    for (int j = 0; j < 8; ++j) {
        const int d = cb + j * 8;
        {
            uint32_t hw, lw;
            split2(o[j][0] * inv0, o[j][1] * inv0, hw, lw);
            const size_t off = ((size_t)(b * SS + r0)) * DM + d;
            *(uint32_t*)(g_ao_hi + off) = hw;
            *(uint32_t*)(g_ao_lo + off) = lw;
        }
        {
            uint32_t hw, lw;
            split2(o[j][2] * inv1, o[j][3] * inv1, hw, lw);
            const size_t off = ((size_t)(b * SS + r0 + 8)) * DM + d;
            *(uint32_t*)(g_ao_hi + off) = hw;
            *(uint32_t*)(g_ao_lo + off) = lw;
        }
    }
}

// ---------------------------------------------------------------------------
extern "C" void kernel_launch(void* const* d_in, const int* in_sizes, int n_in,
                              void* d_out, int out_size)
{
    const float* query = (const float*)d_in[0];
    const float* w_qkv = (const float*)d_in[3];
    const float* w_out = (const float*)d_in[4];
    const float* b_out = (const float*)d_in[5];
    float* out = (float*)d_out;

    static int configured = 0;
    cudaFuncSetAttribute(gemm_ms<1>, cudaFuncAttributeMaxDynamicSharedMemorySize, GEMM_SMEM);
    cudaFuncSetAttribute(gemm_ms<2>, cudaFuncAttributeMaxDynamicSharedMemorySize, GEMM_SMEM);
    cudaFuncSetAttribute(attn_ms,    cudaFuncAttributeMaxDynamicSharedMemorySize, ATTN_SMEM);
    (void)configured;

    // 0) fp32 -> split-bf16
    convert_split<0><<<(NTOK * DM / 4 + 255) / 256, 256>>>(query, NTOK * DM / 4);
    convert_split<1><<<(3 * DM * DM / 4 + 255) / 256, 256>>>(w_qkv, 3 * DM * DM / 4);
    convert_split<2><<<(DM * DM / 4 + 255) / 256, 256>>>(w_out, DM * DM / 4);

    // 1) QKV projection
    {
        dim3 grid(3 * DM / 128, NTOK / 128);
        gemm_ms<1><<<grid, 256, GEMM_SMEM>>>(nullptr, nullptr);
    }
    // 2) attention
    {
        dim3 grid(SS / 128, NH, BB);
        attn_ms<<<grid, 256, ATTN_SMEM>>>();
    }
    // 3) output projection + bias
    {
        dim3 grid(DM / 128, NTOK / 128);
        gemm_ms<2><<<grid, 256, GEMM_SMEM>>>(out, b_out);
    }
}